// round 5
// baseline (speedup 1.0000x reference)
#include <cuda_runtime.h>
#include <math.h>

// Problem dims (fixed)
#define BDIM 128
#define TDIM 512
#define IDIM 512
#define HDIM 1024
#define G4   4096
#define ODIM 512
#define MROWS (BDIM * TDIM)  // 65536

// ---------------- Scratch (static device allocations; no cudaMalloc) ----------
__device__ float g_xg[(size_t)TDIM * BDIM * G4];     // [T,B,4H] 1 GiB
__device__ float g_hout[(size_t)BDIM * TDIM * HDIM]; // [B,T,H] 256 MiB (layer1 out, then layer2 out)
__device__ float g_hA[BDIM * HDIM];                  // recurrent h double buffer
__device__ float g_hB[BDIM * HDIM];

// ---------------- Grid barrier --------------------------------------------
__device__ unsigned g_cnt = 0;
__device__ volatile unsigned g_gen = 0;

__device__ __forceinline__ void grid_barrier(unsigned nb) {
    __syncthreads();
    if (threadIdx.x == 0) {
        unsigned gen = g_gen;
        __threadfence();
        if (atomicAdd(&g_cnt, 1u) == nb - 1u) {
            g_cnt = 0;
            __threadfence();
            g_gen = gen + 1u;
        } else {
            while (g_gen == gen) { }
        }
    }
    __syncthreads();
}

__device__ __forceinline__ float sigmoidf_(float x) {
    return 1.0f / (1.0f + __expf(-x));
}

// ---------------- Feedforward SGEMM: C = A @ W^T + b1 + b2 -----------------
// A: [M, K] row-major, W: [N, K] row-major. 128x128 tile, 8x8 microtile,
// BK=8, double-buffered smem. Optional output row remap (b*T+t) -> (t*B+b).
__global__ __launch_bounds__(256, 2) void gemm_ff(
    const float* __restrict__ A, const float* __restrict__ W,
    const float* __restrict__ b1, const float* __restrict__ b2,
    float* __restrict__ C, int K, int N, int swap)
{
    __shared__ alignas(16) float As[2][8][128];
    __shared__ alignas(16) float Bs[2][8][128];

    const int tid = threadIdx.x;
    const int m0 = blockIdx.y << 7;
    const int n0 = blockIdx.x << 7;
    const int lr = tid >> 1;          // 0..127 tile row for loads
    const int lk = (tid & 1) << 2;    // 0 or 4
    const int ty = tid >> 4;          // 0..15
    const int tx = tid & 15;          // 0..15

    const float* Ap = A + (size_t)(m0 + lr) * K + lk;
    const float* Wp = W + (size_t)(n0 + lr) * K + lk;

    // prologue: k-tile 0
    float4 a4 = *(const float4*)Ap;
    float4 w4 = *(const float4*)Wp;
    As[0][lk + 0][lr] = a4.x; As[0][lk + 1][lr] = a4.y;
    As[0][lk + 2][lr] = a4.z; As[0][lk + 3][lr] = a4.w;
    Bs[0][lk + 0][lr] = w4.x; Bs[0][lk + 1][lr] = w4.y;
    Bs[0][lk + 2][lr] = w4.z; Bs[0][lk + 3][lr] = w4.w;
    __syncthreads();

    float acc[8][8];
#pragma unroll
    for (int i = 0; i < 8; i++)
#pragma unroll
        for (int j = 0; j < 8; j++) acc[i][j] = 0.0f;

    const int nk = K >> 3;
    int cur = 0;
#pragma unroll 1
    for (int kt = 0; kt < nk; ++kt) {
        if (kt + 1 < nk) {
            a4 = *(const float4*)(Ap + ((kt + 1) << 3));
            w4 = *(const float4*)(Wp + ((kt + 1) << 3));
        }
#pragma unroll
        for (int k = 0; k < 8; ++k) {
            float af[8], bf[8];
            *(float4*)(af)     = *(const float4*)&As[cur][k][ty << 3];
            *(float4*)(af + 4) = *(const float4*)&As[cur][k][(ty << 3) + 4];
            *(float4*)(bf)     = *(const float4*)&Bs[cur][k][tx << 3];
            *(float4*)(bf + 4) = *(const float4*)&Bs[cur][k][(tx << 3) + 4];
#pragma unroll
            for (int i = 0; i < 8; i++)
#pragma unroll
                for (int j = 0; j < 8; j++)
                    acc[i][j] = fmaf(af[i], bf[j], acc[i][j]);
        }
        if (kt + 1 < nk) {
            cur ^= 1;
            As[cur][lk + 0][lr] = a4.x; As[cur][lk + 1][lr] = a4.y;
            As[cur][lk + 2][lr] = a4.z; As[cur][lk + 3][lr] = a4.w;
            Bs[cur][lk + 0][lr] = w4.x; Bs[cur][lk + 1][lr] = w4.y;
            Bs[cur][lk + 2][lr] = w4.z; Bs[cur][lk + 3][lr] = w4.w;
            __syncthreads();
        }
    }

    float bias[8];
#pragma unroll
    for (int j = 0; j < 8; j++) {
        int n = n0 + (tx << 3) + j;
        float bb = b1 ? b1[n] : 0.0f;
        if (b2) bb += b2[n];
        bias[j] = bb;
    }
#pragma unroll
    for (int i = 0; i < 8; i++) {
        int r = m0 + (ty << 3) + i;                       // r = b*T + t
        int orow = swap ? ((r & (TDIM - 1)) * BDIM + (r >> 9)) : r;
        float* Cp = C + (size_t)orow * N + n0 + (tx << 3);
        float4 v0 = make_float4(acc[i][0] + bias[0], acc[i][1] + bias[1],
                                acc[i][2] + bias[2], acc[i][3] + bias[3]);
        float4 v1 = make_float4(acc[i][4] + bias[4], acc[i][5] + bias[5],
                                acc[i][6] + bias[6], acc[i][7] + bias[7]);
        *(float4*)Cp = v0;
        *(float4*)(Cp + 4) = v1;
    }
}

// ---------------- Persistent LSTM scan -------------------------------------
// Grid = 128 CTAs (4 b-tiles x 32 h-tiles), 256 threads. Each CTA owns a
// 32(b) x 32(h) cell block; gate GEMM tile is 32(b) x 128 cols (4 gates x 32 h),
// K=1024 over previous h. c state lives in smem for the whole scan. One grid
// barrier per timestep. Cross-step h reads via __ldcg (L1 non-coherent).
__global__ __launch_bounds__(256, 1) void lstm_scan(const float* __restrict__ Whh)
{
    __shared__ alignas(16) float As[2][16][36];   // [k][b], padded
    __shared__ alignas(16) float Bs[2][16][128];  // [k][col]
    __shared__ alignas(16) float gsm[32][128];    // gates staging
    __shared__ float csm[32][32];                 // cell state (persistent)

    const int tid = threadIdx.x;
    const int b0 = (blockIdx.x >> 5) << 5;  // 0,32,64,96
    const int h0 = (blockIdx.x & 31) << 5;  // 0..992
    const unsigned nb = gridDim.x;

    // zero c and the initial h buffer (this CTA's (b,h) block)
    for (int q = tid; q < 1024; q += 256) {
        csm[q >> 5][q & 31] = 0.0f;
        g_hA[(b0 + (q >> 5)) * HDIM + h0 + (q & 31)] = 0.0f;
    }
    __threadfence();
    grid_barrier(nb);

    // compute-thread mapping: 8x32 threads, 4x4 microtile
    const int ty = tid >> 5;         // 0..7  -> b rows ty*4..+3
    const int tx = tid & 31;         // 0..31 -> cols tx*4..+3

    // A-load mapping (threads 0..127): 32 b x 16 k per tile
    const int ab = tid >> 2;         // row within tile (valid < 32 when tid<128)
    const int ak = (tid & 3) << 2;   // k offset {0,4,8,12}

    // B-load mapping: 128 cols x 16 k = 512 float4, 2 per thread
    const int col0 = tid >> 2;              // 0..63
    const int col1 = (tid + 256) >> 2;      // 64..127
    const int kb = (tid & 3) << 2;          // k offset
    const int wrow0 = ((col0 >> 5) << 10) + h0 + (col0 & 31);  // gate*1024 + h
    const int wrow1 = ((col1 >> 5) << 10) + h0 + (col1 & 31);
    const float* Wp0 = Whh + (size_t)wrow0 * HDIM + kb;
    const float* Wp1 = Whh + (size_t)wrow1 * HDIM + kb;

    // elementwise mapping: 4 cells per thread
    const int eb = tid >> 3;           // 0..31
    const int ehh = (tid & 7) << 2;    // 0..28

#pragma unroll 1
    for (int t = 0; t < TDIM; ++t) {
        const float* hp = (t & 1) ? g_hB : g_hA;
        float* hn = (t & 1) ? g_hA : g_hB;
        const float* Ap = hp + (b0 + ab) * HDIM + ak;

        // prologue: k-tile 0
        float4 ra = make_float4(0.f, 0.f, 0.f, 0.f);
        if (tid < 128) ra = __ldcg((const float4*)Ap);
        float4 rb0 = *(const float4*)Wp0;
        float4 rb1 = *(const float4*)Wp1;
        if (tid < 128) {
            As[0][ak + 0][ab] = ra.x; As[0][ak + 1][ab] = ra.y;
            As[0][ak + 2][ab] = ra.z; As[0][ak + 3][ab] = ra.w;
        }
        Bs[0][kb + 0][col0] = rb0.x; Bs[0][kb + 1][col0] = rb0.y;
        Bs[0][kb + 2][col0] = rb0.z; Bs[0][kb + 3][col0] = rb0.w;
        Bs[0][kb + 0][col1] = rb1.x; Bs[0][kb + 1][col1] = rb1.y;
        Bs[0][kb + 2][col1] = rb1.z; Bs[0][kb + 3][col1] = rb1.w;
        __syncthreads();

        float acc[4][4];
#pragma unroll
        for (int i = 0; i < 4; i++)
#pragma unroll
            for (int j = 0; j < 4; j++) acc[i][j] = 0.0f;

        int cur = 0;
#pragma unroll 1
        for (int kt = 0; kt < 64; ++kt) {
            if (kt < 63) {
                int ko = (kt + 1) << 4;
                if (tid < 128) ra = __ldcg((const float4*)(Ap + ko));
                rb0 = *(const float4*)(Wp0 + ko);
                rb1 = *(const float4*)(Wp1 + ko);
            }
#pragma unroll
            for (int k = 0; k < 16; ++k) {
                float4 a = *(const float4*)&As[cur][k][ty << 2];
                float4 b = *(const float4*)&Bs[cur][k][tx << 2];
                acc[0][0] = fmaf(a.x, b.x, acc[0][0]);
                acc[0][1] = fmaf(a.x, b.y, acc[0][1]);
                acc[0][2] = fmaf(a.x, b.z, acc[0][2]);
                acc[0][3] = fmaf(a.x, b.w, acc[0][3]);
                acc[1][0] = fmaf(a.y, b.x, acc[1][0]);
                acc[1][1] = fmaf(a.y, b.y, acc[1][1]);
                acc[1][2] = fmaf(a.y, b.z, acc[1][2]);
                acc[1][3] = fmaf(a.y, b.w, acc[1][3]);
                acc[2][0] = fmaf(a.z, b.x, acc[2][0]);
                acc[2][1] = fmaf(a.z, b.y, acc[2][1]);
                acc[2][2] = fmaf(a.z, b.z, acc[2][2]);
                acc[2][3] = fmaf(a.z, b.w, acc[2][3]);
                acc[3][0] = fmaf(a.w, b.x, acc[3][0]);
                acc[3][1] = fmaf(a.w, b.y, acc[3][1]);
                acc[3][2] = fmaf(a.w, b.z, acc[3][2]);
                acc[3][3] = fmaf(a.w, b.w, acc[3][3]);
            }
            if (kt < 63) {
                cur ^= 1;
                if (tid < 128) {
                    As[cur][ak + 0][ab] = ra.x; As[cur][ak + 1][ab] = ra.y;
                    As[cur][ak + 2][ab] = ra.z; As[cur][ak + 3][ab] = ra.w;
                }
                Bs[cur][kb + 0][col0] = rb0.x; Bs[cur][kb + 1][col0] = rb0.y;
                Bs[cur][kb + 2][col0] = rb0.z; Bs[cur][kb + 3][col0] = rb0.w;
                Bs[cur][kb + 0][col1] = rb1.x; Bs[cur][kb + 1][col1] = rb1.y;
                Bs[cur][kb + 2][col1] = rb1.z; Bs[cur][kb + 3][col1] = rb1.w;
                __syncthreads();
            }
        }

        // stage gates to smem for the gate-regrouped elementwise
#pragma unroll
        for (int i = 0; i < 4; i++) {
            *(float4*)&gsm[(ty << 2) + i][tx << 2] =
                make_float4(acc[i][0], acc[i][1], acc[i][2], acc[i][3]);
        }
        __syncthreads();

        {
            const size_t xb = ((size_t)t * BDIM + b0 + eb) * G4 + h0 + ehh;
            float4 xi = *(const float4*)&g_xg[xb];
            float4 xf = *(const float4*)&g_xg[xb + 1024];
            float4 xg2 = *(const float4*)&g_xg[xb + 2048];
            float4 xo = *(const float4*)&g_xg[xb + 3072];
            const float* pxi = (const float*)&xi;
            const float* pxf = (const float*)&xf;
            const float* pxg = (const float*)&xg2;
            const float* pxo = (const float*)&xo;

            float h4[4];
#pragma unroll
            for (int q = 0; q < 4; q++) {
                int hh = ehh + q;
                float gi = gsm[eb][hh]      + pxi[q];
                float gf = gsm[eb][32 + hh] + pxf[q];
                float gg = gsm[eb][64 + hh] + pxg[q];
                float go = gsm[eb][96 + hh] + pxo[q];
                gi = sigmoidf_(gi);
                gf = sigmoidf_(gf);
                gg = tanhf(gg);
                go = sigmoidf_(go);
                float c = fmaf(gf, csm[eb][hh], gi * gg);
                csm[eb][hh] = c;
                h4[q] = go * tanhf(c);
            }
            float4 hv = make_float4(h4[0], h4[1], h4[2], h4[3]);
            *(float4*)&hn[(b0 + eb) * HDIM + h0 + ehh] = hv;
            *(float4*)&g_hout[((size_t)(b0 + eb) * TDIM + t) * HDIM + h0 + ehh] = hv;
        }
        __threadfence();
        grid_barrier(nb);
    }
}

// ---------------- Launch orchestration -------------------------------------
extern "C" void kernel_launch(void* const* d_in, const int* in_sizes, int n_in,
                              void* d_out, int out_size)
{
    (void)in_sizes; (void)n_in; (void)out_size;
    const float* x    = (const float*)d_in[0];
    const float* Wih0 = (const float*)d_in[1];
    const float* Whh0 = (const float*)d_in[2];
    const float* bih0 = (const float*)d_in[3];
    const float* bhh0 = (const float*)d_in[4];
    const float* Wih1 = (const float*)d_in[5];
    const float* Whh1 = (const float*)d_in[6];
    const float* bih1 = (const float*)d_in[7];
    const float* bhh1 = (const float*)d_in[8];
    const float* Wlin = (const float*)d_in[9];
    const float* blin = (const float*)d_in[10];
    float* out = (float*)d_out;

    void *pxg = nullptr, *phout = nullptr;
    cudaGetSymbolAddress(&pxg, g_xg);
    cudaGetSymbolAddress(&phout, g_hout);
    float* xg = (float*)pxg;
    float* hout = (float*)phout;

    // Layer 0: xg0[T,B,4H] = X @ W_ih0^T + b_ih0 + b_hh0
    gemm_ff<<<dim3(G4 / 128, MROWS / 128), 256>>>(x, Wih0, bih0, bhh0, xg, IDIM, G4, 1);
    // Layer 0 scan -> g_hout [B,T,H]
    lstm_scan<<<128, 256>>>(Whh0);
    // Layer 1: xg1[T,B,4H] = h1 @ W_ih1^T + b_ih1 + b_hh1
    gemm_ff<<<dim3(G4 / 128, MROWS / 128), 256>>>(hout, Wih1, bih1, bhh1, xg, HDIM, G4, 1);
    // Layer 1 scan -> g_hout (overwrites h1; safe, xg1 already materialized)
    lstm_scan<<<128, 256>>>(Whh1);
    // Output: out[B,T,O] = h2 @ W_lin^T + b_lin
    gemm_ff<<<dim3(ODIM / 128, MROWS / 128), 256>>>(hout, Wlin, blin, nullptr, out, HDIM, ODIM, 0);
}

// round 6
// speedup vs baseline: 1.0027x; 1.0027x over previous
#include <cuda_runtime.h>
#include <math.h>

// Problem dims (fixed)
#define BDIM 128
#define TDIM 512
#define IDIM 512
#define HDIM 1024
#define G4   4096
#define ODIM 512
#define MROWS (BDIM * TDIM)  // 65536

// ---------------- Scratch (static device allocations; no cudaMalloc) ----------
__device__ float g_xg[(size_t)TDIM * BDIM * G4];     // [T,B,4H] 1 GiB
__device__ float g_hout[(size_t)BDIM * TDIM * HDIM]; // [B,T,H] 256 MiB (layer1 out, then layer2 out)
__device__ float g_hA[BDIM * HDIM];                  // recurrent h double buffer
__device__ float g_hB[BDIM * HDIM];

// ---------------- Grid barrier --------------------------------------------
__device__ unsigned g_cnt = 0;
__device__ volatile unsigned g_gen = 0;

__device__ __forceinline__ void grid_barrier(unsigned nb) {
    __syncthreads();
    if (threadIdx.x == 0) {
        unsigned gen = g_gen;
        __threadfence();
        if (atomicAdd(&g_cnt, 1u) == nb - 1u) {
            g_cnt = 0;
            __threadfence();
            g_gen = gen + 1u;
        } else {
            while (g_gen == gen) { }
        }
    }
    __syncthreads();
}

__device__ __forceinline__ float sigmoidf_(float x) {
    return 1.0f / (1.0f + __expf(-x));
}

// ---------------- Feedforward SGEMM: C = A @ W^T + b1 + b2 -----------------
// A: [M, K] row-major, W: [N, K] row-major. 128x128 tile, 8x8 microtile,
// BK=8, double-buffered smem. Optional output row remap (b*T+t) -> (t*B+b).
__global__ __launch_bounds__(256, 2) void gemm_ff(
    const float* __restrict__ A, const float* __restrict__ W,
    const float* __restrict__ b1, const float* __restrict__ b2,
    float* __restrict__ C, int K, int N, int swap)
{
    __shared__ alignas(16) float As[2][8][128];
    __shared__ alignas(16) float Bs[2][8][128];

    const int tid = threadIdx.x;
    const int m0 = blockIdx.y << 7;
    const int n0 = blockIdx.x << 7;
    const int lr = tid >> 1;          // 0..127 tile row for loads
    const int lk = (tid & 1) << 2;    // 0 or 4
    const int ty = tid >> 4;          // 0..15
    const int tx = tid & 15;          // 0..15

    const float* Ap = A + (size_t)(m0 + lr) * K + lk;
    const float* Wp = W + (size_t)(n0 + lr) * K + lk;

    // prologue: k-tile 0
    float4 a4 = *(const float4*)Ap;
    float4 w4 = *(const float4*)Wp;
    As[0][lk + 0][lr] = a4.x; As[0][lk + 1][lr] = a4.y;
    As[0][lk + 2][lr] = a4.z; As[0][lk + 3][lr] = a4.w;
    Bs[0][lk + 0][lr] = w4.x; Bs[0][lk + 1][lr] = w4.y;
    Bs[0][lk + 2][lr] = w4.z; Bs[0][lk + 3][lr] = w4.w;
    __syncthreads();

    float acc[8][8];
#pragma unroll
    for (int i = 0; i < 8; i++)
#pragma unroll
        for (int j = 0; j < 8; j++) acc[i][j] = 0.0f;

    const int nk = K >> 3;
    int cur = 0;
#pragma unroll 1
    for (int kt = 0; kt < nk; ++kt) {
        if (kt + 1 < nk) {
            a4 = *(const float4*)(Ap + ((kt + 1) << 3));
            w4 = *(const float4*)(Wp + ((kt + 1) << 3));
        }
#pragma unroll
        for (int k = 0; k < 8; ++k) {
            float af[8], bf[8];
            *(float4*)(af)     = *(const float4*)&As[cur][k][ty << 3];
            *(float4*)(af + 4) = *(const float4*)&As[cur][k][(ty << 3) + 4];
            *(float4*)(bf)     = *(const float4*)&Bs[cur][k][tx << 3];
            *(float4*)(bf + 4) = *(const float4*)&Bs[cur][k][(tx << 3) + 4];
#pragma unroll
            for (int i = 0; i < 8; i++)
#pragma unroll
                for (int j = 0; j < 8; j++)
                    acc[i][j] = fmaf(af[i], bf[j], acc[i][j]);
        }
        if (kt + 1 < nk) {
            cur ^= 1;
            As[cur][lk + 0][lr] = a4.x; As[cur][lk + 1][lr] = a4.y;
            As[cur][lk + 2][lr] = a4.z; As[cur][lk + 3][lr] = a4.w;
            Bs[cur][lk + 0][lr] = w4.x; Bs[cur][lk + 1][lr] = w4.y;
            Bs[cur][lk + 2][lr] = w4.z; Bs[cur][lk + 3][lr] = w4.w;
            __syncthreads();
        }
    }

    float bias[8];
#pragma unroll
    for (int j = 0; j < 8; j++) {
        int n = n0 + (tx << 3) + j;
        float bb = b1 ? b1[n] : 0.0f;
        if (b2) bb += b2[n];
        bias[j] = bb;
    }
#pragma unroll
    for (int i = 0; i < 8; i++) {
        int r = m0 + (ty << 3) + i;                       // r = b*T + t
        int orow = swap ? ((r & (TDIM - 1)) * BDIM + (r >> 9)) : r;
        float* Cp = C + (size_t)orow * N + n0 + (tx << 3);
        float4 v0 = make_float4(acc[i][0] + bias[0], acc[i][1] + bias[1],
                                acc[i][2] + bias[2], acc[i][3] + bias[3]);
        float4 v1 = make_float4(acc[i][4] + bias[4], acc[i][5] + bias[5],
                                acc[i][6] + bias[6], acc[i][7] + bias[7]);
        *(float4*)Cp = v0;
        *(float4*)(Cp + 4) = v1;
    }
}

// ---------------- Persistent LSTM scan -------------------------------------
// Grid = 128 CTAs (4 b-tiles x 32 h-tiles), 256 threads. Each CTA owns a
// 32(b) x 32(h) cell block; gate GEMM tile is 32(b) x 128 cols (4 gates x 32 h),
// K=1024 over previous h. c state lives in smem for the whole scan. One grid
// barrier per timestep. Cross-step h reads via __ldcg (L1 non-coherent).
__global__ __launch_bounds__(256, 1) void lstm_scan(const float* __restrict__ Whh)
{
    __shared__ alignas(16) float As[2][16][36];   // [k][b], padded
    __shared__ alignas(16) float Bs[2][16][128];  // [k][col]
    __shared__ alignas(16) float gsm[32][128];    // gates staging
    __shared__ float csm[32][32];                 // cell state (persistent)

    const int tid = threadIdx.x;
    const int b0 = (blockIdx.x >> 5) << 5;  // 0,32,64,96
    const int h0 = (blockIdx.x & 31) << 5;  // 0..992
    const unsigned nb = gridDim.x;

    // zero c and the initial h buffer (this CTA's (b,h) block)
    for (int q = tid; q < 1024; q += 256) {
        csm[q >> 5][q & 31] = 0.0f;
        g_hA[(b0 + (q >> 5)) * HDIM + h0 + (q & 31)] = 0.0f;
    }
    __threadfence();
    grid_barrier(nb);

    // compute-thread mapping: 8x32 threads, 4x4 microtile
    const int ty = tid >> 5;         // 0..7  -> b rows ty*4..+3
    const int tx = tid & 31;         // 0..31 -> cols tx*4..+3

    // A-load mapping (threads 0..127): 32 b x 16 k per tile
    const int ab = tid >> 2;         // row within tile (valid < 32 when tid<128)
    const int ak = (tid & 3) << 2;   // k offset {0,4,8,12}

    // B-load mapping: 128 cols x 16 k = 512 float4, 2 per thread
    const int col0 = tid >> 2;              // 0..63
    const int col1 = (tid + 256) >> 2;      // 64..127
    const int kb = (tid & 3) << 2;          // k offset
    const int wrow0 = ((col0 >> 5) << 10) + h0 + (col0 & 31);  // gate*1024 + h
    const int wrow1 = ((col1 >> 5) << 10) + h0 + (col1 & 31);
    const float* Wp0 = Whh + (size_t)wrow0 * HDIM + kb;
    const float* Wp1 = Whh + (size_t)wrow1 * HDIM + kb;

    // elementwise mapping: 4 cells per thread
    const int eb = tid >> 3;           // 0..31
    const int ehh = (tid & 7) << 2;    // 0..28

#pragma unroll 1
    for (int t = 0; t < TDIM; ++t) {
        const float* hp = (t & 1) ? g_hB : g_hA;
        float* hn = (t & 1) ? g_hA : g_hB;
        const float* Ap = hp + (b0 + ab) * HDIM + ak;

        // prologue: k-tile 0
        float4 ra = make_float4(0.f, 0.f, 0.f, 0.f);
        if (tid < 128) ra = __ldcg((const float4*)Ap);
        float4 rb0 = *(const float4*)Wp0;
        float4 rb1 = *(const float4*)Wp1;
        if (tid < 128) {
            As[0][ak + 0][ab] = ra.x; As[0][ak + 1][ab] = ra.y;
            As[0][ak + 2][ab] = ra.z; As[0][ak + 3][ab] = ra.w;
        }
        Bs[0][kb + 0][col0] = rb0.x; Bs[0][kb + 1][col0] = rb0.y;
        Bs[0][kb + 2][col0] = rb0.z; Bs[0][kb + 3][col0] = rb0.w;
        Bs[0][kb + 0][col1] = rb1.x; Bs[0][kb + 1][col1] = rb1.y;
        Bs[0][kb + 2][col1] = rb1.z; Bs[0][kb + 3][col1] = rb1.w;
        __syncthreads();

        float acc[4][4];
#pragma unroll
        for (int i = 0; i < 4; i++)
#pragma unroll
            for (int j = 0; j < 4; j++) acc[i][j] = 0.0f;

        int cur = 0;
#pragma unroll 1
        for (int kt = 0; kt < 64; ++kt) {
            if (kt < 63) {
                int ko = (kt + 1) << 4;
                if (tid < 128) ra = __ldcg((const float4*)(Ap + ko));
                rb0 = *(const float4*)(Wp0 + ko);
                rb1 = *(const float4*)(Wp1 + ko);
            }
#pragma unroll
            for (int k = 0; k < 16; ++k) {
                float4 a = *(const float4*)&As[cur][k][ty << 2];
                float4 b = *(const float4*)&Bs[cur][k][tx << 2];
                acc[0][0] = fmaf(a.x, b.x, acc[0][0]);
                acc[0][1] = fmaf(a.x, b.y, acc[0][1]);
                acc[0][2] = fmaf(a.x, b.z, acc[0][2]);
                acc[0][3] = fmaf(a.x, b.w, acc[0][3]);
                acc[1][0] = fmaf(a.y, b.x, acc[1][0]);
                acc[1][1] = fmaf(a.y, b.y, acc[1][1]);
                acc[1][2] = fmaf(a.y, b.z, acc[1][2]);
                acc[1][3] = fmaf(a.y, b.w, acc[1][3]);
                acc[2][0] = fmaf(a.z, b.x, acc[2][0]);
                acc[2][1] = fmaf(a.z, b.y, acc[2][1]);
                acc[2][2] = fmaf(a.z, b.z, acc[2][2]);
                acc[2][3] = fmaf(a.z, b.w, acc[2][3]);
                acc[3][0] = fmaf(a.w, b.x, acc[3][0]);
                acc[3][1] = fmaf(a.w, b.y, acc[3][1]);
                acc[3][2] = fmaf(a.w, b.z, acc[3][2]);
                acc[3][3] = fmaf(a.w, b.w, acc[3][3]);
            }
            if (kt < 63) {
                cur ^= 1;
                if (tid < 128) {
                    As[cur][ak + 0][ab] = ra.x; As[cur][ak + 1][ab] = ra.y;
                    As[cur][ak + 2][ab] = ra.z; As[cur][ak + 3][ab] = ra.w;
                }
                Bs[cur][kb + 0][col0] = rb0.x; Bs[cur][kb + 1][col0] = rb0.y;
                Bs[cur][kb + 2][col0] = rb0.z; Bs[cur][kb + 3][col0] = rb0.w;
                Bs[cur][kb + 0][col1] = rb1.x; Bs[cur][kb + 1][col1] = rb1.y;
                Bs[cur][kb + 2][col1] = rb1.z; Bs[cur][kb + 3][col1] = rb1.w;
                __syncthreads();
            }
        }

        // stage gates to smem for the gate-regrouped elementwise
#pragma unroll
        for (int i = 0; i < 4; i++) {
            *(float4*)&gsm[(ty << 2) + i][tx << 2] =
                make_float4(acc[i][0], acc[i][1], acc[i][2], acc[i][3]);
        }
        __syncthreads();

        {
            const size_t xb = ((size_t)t * BDIM + b0 + eb) * G4 + h0 + ehh;
            float4 xi = *(const float4*)&g_xg[xb];
            float4 xf = *(const float4*)&g_xg[xb + 1024];
            float4 xg2 = *(const float4*)&g_xg[xb + 2048];
            float4 xo = *(const float4*)&g_xg[xb + 3072];
            const float* pxi = (const float*)&xi;
            const float* pxf = (const float*)&xf;
            const float* pxg = (const float*)&xg2;
            const float* pxo = (const float*)&xo;

            float h4[4];
#pragma unroll
            for (int q = 0; q < 4; q++) {
                int hh = ehh + q;
                float gi = gsm[eb][hh]      + pxi[q];
                float gf = gsm[eb][32 + hh] + pxf[q];
                float gg = gsm[eb][64 + hh] + pxg[q];
                float go = gsm[eb][96 + hh] + pxo[q];
                gi = sigmoidf_(gi);
                gf = sigmoidf_(gf);
                gg = tanhf(gg);
                go = sigmoidf_(go);
                float c = fmaf(gf, csm[eb][hh], gi * gg);
                csm[eb][hh] = c;
                h4[q] = go * tanhf(c);
            }
            float4 hv = make_float4(h4[0], h4[1], h4[2], h4[3]);
            *(float4*)&hn[(b0 + eb) * HDIM + h0 + ehh] = hv;
            *(float4*)&g_hout[((size_t)(b0 + eb) * TDIM + t) * HDIM + h0 + ehh] = hv;
        }
        __threadfence();
        grid_barrier(nb);
    }
}

// ---------------- Launch orchestration -------------------------------------
extern "C" void kernel_launch(void* const* d_in, const int* in_sizes, int n_in,
                              void* d_out, int out_size)
{
    (void)in_sizes; (void)n_in; (void)out_size;
    const float* x    = (const float*)d_in[0];
    const float* Wih0 = (const float*)d_in[1];
    const float* Whh0 = (const float*)d_in[2];
    const float* bih0 = (const float*)d_in[3];
    const float* bhh0 = (const float*)d_in[4];
    const float* Wih1 = (const float*)d_in[5];
    const float* Whh1 = (const float*)d_in[6];
    const float* bih1 = (const float*)d_in[7];
    const float* bhh1 = (const float*)d_in[8];
    const float* Wlin = (const float*)d_in[9];
    const float* blin = (const float*)d_in[10];
    float* out = (float*)d_out;

    void *pxg = nullptr, *phout = nullptr;
    cudaGetSymbolAddress(&pxg, g_xg);
    cudaGetSymbolAddress(&phout, g_hout);
    float* xg = (float*)pxg;
    float* hout = (float*)phout;

    // Layer 0: xg0[T,B,4H] = X @ W_ih0^T + b_ih0 + b_hh0
    gemm_ff<<<dim3(G4 / 128, MROWS / 128), 256>>>(x, Wih0, bih0, bhh0, xg, IDIM, G4, 1);
    // Layer 0 scan -> g_hout [B,T,H]
    lstm_scan<<<128, 256>>>(Whh0);
    // Layer 1: xg1[T,B,4H] = h1 @ W_ih1^T + b_ih1 + b_hh1
    gemm_ff<<<dim3(G4 / 128, MROWS / 128), 256>>>(hout, Wih1, bih1, bhh1, xg, HDIM, G4, 1);
    // Layer 1 scan -> g_hout (overwrites h1; safe, xg1 already materialized)
    lstm_scan<<<128, 256>>>(Whh1);
    // Output: out[B,T,O] = h2 @ W_lin^T + b_lin
    gemm_ff<<<dim3(ODIM / 128, MROWS / 128), 256>>>(hout, Wlin, blin, nullptr, out, HDIM, ODIM, 0);
}